// round 15
// baseline (speedup 1.0000x reference)
#include <cuda_runtime.h>
#include <cuda_fp16.h>
#include <math.h>
#include <stdint.h>

// ---------------------------------------------------------------------------
// Problem constants
// ---------------------------------------------------------------------------
#define NB   64
#define CCH  64
#define TT   300
#define VV   25
#define SS   3
#define IC   16
#define TV   (TT*VV)          // 7500
#define KROWS (IC*TT)         // 4800
#define KS   3
#define KPB  (KROWS/KS)       // 1600
#define ACH  160

// Scratch (device globals — no allocation allowed)
__device__ __half  g_t1h[SS * NB * IC * TV];
__device__ __half  g_t2h[SS * NB * IC * TV];
__device__ float   g_A1[SS * NB * VV * VV];
__device__ float   g_Afull[SS * VV * VV];
__device__ __half2 g_Whd[SS * 576 * 32];
__device__ float   g_plog[SS * NB * KS * 640];

// ---------------------------------------------------------------------------
// Packed fp32x2 helpers
// ---------------------------------------------------------------------------
__device__ __forceinline__ void fma2(uint64_t& d, uint64_t a, uint64_t b) {
    asm("fma.rn.f32x2 %0, %1, %2, %0;" : "+l"(d) : "l"(a), "l"(b));
}
__device__ __forceinline__ void add2(uint64_t& d, uint64_t a) {
    asm("add.rn.f32x2 %0, %0, %1;" : "+l"(d) : "l"(a));
}
__device__ __forceinline__ uint64_t pack2(float lo, float hi) {
    uint64_t r;
    asm("mov.b64 %0, {%1, %2};" : "=l"(r) : "f"(lo), "f"(hi));
    return r;
}
__device__ __forceinline__ float2 unpack2(uint64_t v) {
    float2 r;
    asm("mov.b64 {%0, %1}, %2;" : "=f"(r.x), "=f"(r.y) : "l"(v));
    return r;
}

// ---------------------------------------------------------------------------
// K0: A_full = A + PA + (8A^4 - 4A^2 - 4A + I)
// ---------------------------------------------------------------------------
__global__ void k_afull(const float* __restrict__ A, const float* __restrict__ PA) {
    for (int idx = threadIdx.x; idx < SS * VV * VV; idx += blockDim.x) {
        int r = idx % (VV * VV);
        int v1 = r / VV, v2 = r % VV;
        float a = A[idx];
        float a2 = a * a;
        float ch = 8.f * a2 * a2 - 4.f * a2 - 4.f * a + (v1 == v2 ? 1.f : 0.f);
        g_Afull[idx] = a + PA[idx] + ch;
    }
}

// ---------------------------------------------------------------------------
// K0b: pre-duplicate conv weights to half2(w,w)
// ---------------------------------------------------------------------------
__global__ void k_wprep(const float* __restrict__ WT1, const float* __restrict__ WT2) {
    for (int idx = threadIdx.x + blockIdx.x * blockDim.x; idx < SS * 576 * 32;
         idx += blockDim.x * gridDim.x) {
        int slot = idx & 31;
        int kd   = (idx >> 5) % 576;
        int s    = idx / (576 * 32);
        int ci = kd / 9, dt = kd - 9 * (kd / 9);
        int cv = slot >> 4, co = slot & 15;
        float w = cv ? WT2[((s * IC + co) * CCH + ci) * 9 + dt]
                     : WT1[((s * IC + co) * CCH + ci) * 9 + dt];
        __half h = __float2half(w);
        g_Whd[idx] = __halves2half2(h, h);
    }
}

// ---------------------------------------------------------------------------
// K1 v7: slim_conv HFMA2. Thread = 16 co-slots x 10 t (one full conv).
// grid (6, N, S); block 250; smem 73728 B; 2 CTAs/SM.
// ---------------------------------------------------------------------------
__global__ __launch_bounds__(250, 2)
void k_conv(const float* __restrict__ x,
            const float* __restrict__ bT1, const float* __restrict__ bT2,
            const float* __restrict__ weights) {
    const int s = blockIdx.z;
    const int n = blockIdx.y;
    extern __shared__ __half2 sw[];   // 576*32 half2 = 73728 B

    {
        const uint4* src = (const uint4*)(g_Whd + s * 576 * 32);
        uint4* dst = (uint4*)sw;
        for (int i = threadIdx.x; i < 576 * 32 / 4; i += 250) dst[i] = src[i];
    }
    __syncthreads();

    const int tid = threadIdx.x;
    const int cog = tid / 125;           // 0..1  (= cv)
    const int r   = tid - cog * 125;
    const int tg  = r / 25;              // 0..4
    const int v   = r - tg * 25;
    const int t0  = blockIdx.x * 50 + tg * 10;
    const bool interior = (t0 >= 4) && (t0 + 13 < TT);

    half2 hacc[80];                      // [j 0..15][tp 0..4]
    const half2 hz = __float2half2_rn(0.f);
#pragma unroll
    for (int i = 0; i < 80; i++) hacc[i] = hz;

    const float* xb = x + n * CCH * TV + v;

    for (int ci = 0; ci < CCH; ci++) {
        const float* xp = xb + ci * TV + (t0 - 4) * VV;
        float xr[18];
        if (interior) {
#pragma unroll
            for (int k = 0; k < 18; k++) xr[k] = __ldg(xp + k * VV);
        } else {
#pragma unroll
            for (int k = 0; k < 18; k++) {
                int tt = t0 - 4 + k;
                xr[k] = (tt >= 0 && tt < TT) ? __ldg(xp + k * VV) : 0.f;
            }
        }
        half2 xe[9], xo[8];
#pragma unroll
        for (int j = 0; j < 9; j++) xe[j] = __floats2half2_rn(xr[2 * j], xr[2 * j + 1]);
#pragma unroll
        for (int j = 0; j < 8; j++) xo[j] = __floats2half2_rn(xr[2 * j + 1], xr[2 * j + 2]);

#pragma unroll
        for (int dt = 0; dt < 9; dt++) {
            const uint4* wp = (const uint4*)(sw + (ci * 9 + dt) * 32 + cog * 16);
            half2 w[16];
            *(uint4*)(w)      = wp[0];
            *(uint4*)(w + 4)  = wp[1];
            *(uint4*)(w + 8)  = wp[2];
            *(uint4*)(w + 12) = wp[3];
            const half2* xv = (dt & 1) ? (xo + (dt >> 1)) : (xe + (dt >> 1));
#pragma unroll
            for (int j = 0; j < 16; j++) {
#pragma unroll
                for (int tp = 0; tp < 5; tp++) {
                    hacc[j * 5 + tp] = __hfma2(w[j], xv[tp], hacc[j * 5 + tp]);
                }
            }
        }
    }

    const float ws1 = __ldg(weights + 1), ws2 = __ldg(weights + 2);
    const float ws3 = __ldg(weights + 3), ws4 = __ldg(weights + 4);
    const float* bsrc = cog ? bT2 : bT1;
    __half* gout = cog ? g_t2h : g_t1h;
    const size_t obase = (size_t)(s * NB + n) * IC * TV + v;
#pragma unroll
    for (int j = 0; j < 16; j++) {
        int co = j;
        // slim splits for out_c=16: 9, 11, 12, 14
        float sc = (co < 9) ? 1.f : (co < 11) ? ws1 : (co < 12) ? ws2 : (co < 14) ? ws3 : ws4;
        float b = __ldg(bsrc + s * IC + co);
        size_t oc = obase + (size_t)co * TV + (size_t)t0 * VV;
#pragma unroll
        for (int tp = 0; tp < 5; tp++) {
            float2 f = __half22float2(hacc[j * 5 + tp]);
            gout[oc + (2 * tp) * VV]     = __float2half(sc * (f.x + b));
            gout[oc + (2 * tp + 1) * VV] = __float2half(sc * (f.y + b));
        }
    }
}

// ---------------------------------------------------------------------------
// K2a: attention partial logits.  grid (N, S, KS), block 640.
// ---------------------------------------------------------------------------
__global__ __launch_bounds__(640, 2)
void k_att2() {
    const int n  = blockIdx.x;
    const int s  = blockIdx.y;
    const int kc = blockIdx.z;
    __shared__ __half s1t[25 * 166];
    __shared__ __half s2t[25 * 166];

    const __half* t1b = g_t1h + (size_t)(s * NB + n) * IC * TV;
    const __half* t2b = g_t2h + (size_t)(s * NB + n) * IC * TV;

    const int tid = threadIdx.x;
    const int v1 = tid / 25;
    const int v2 = tid - v1 * 25;
    const bool act = tid < VV * VV;
    float acc = 0.f;

    for (int ch = 0; ch < KPB / ACH; ch++) {
        const int kbase = kc * KPB + ch * ACH;
        for (int idx = tid; idx < ACH * VV; idx += 640) {
            int kk = idx / VV;
            int v  = idx - kk * VV;
            int k  = kbase + kk;
            int c  = k / TT;
            int t  = k - c * TT;
            int off = c * TV + t * VV + v;
            s1t[v * 166 + kk] = t1b[off];
            s2t[v * 166 + kk] = t2b[off];
        }
        __syncthreads();
        if (act) {
            const half2* p1 = (const half2*)s1t + v1 * 83;
            const half2* p2 = (const half2*)s2t + v2 * 83;
#pragma unroll
            for (int g = 0; g < 5; g++) {
                half2 ph = __float2half2_rn(0.f);
#pragma unroll
                for (int j = 0; j < 16; j++)
                    ph = __hfma2(p1[g * 16 + j], p2[g * 16 + j], ph);
                float2 f = __half22float2(ph);
                acc += f.x + f.y;
            }
        }
        __syncthreads();
    }

    g_plog[((size_t)(s * NB + n) * KS + kc) * 640 + tid] = acc;
}

// ---------------------------------------------------------------------------
// K2b: reduce partials + softmax(axis=-2 over v1) + A_full -> A1
// ---------------------------------------------------------------------------
__global__ __launch_bounds__(640, 2)
void k_soft() {
    const int n = blockIdx.x;
    const int s = blockIdx.y;
    __shared__ float sl[VV * VV];
    const int tid = threadIdx.x;

    if (tid < VV * VV) {
        const float* pb = g_plog + (size_t)(s * NB + n) * KS * 640 + tid;
        float a = pb[0] + pb[640] + pb[1280];
        sl[tid] = a * (1.0f / (float)KROWS);
    }
    __syncthreads();

    if (tid < VV) {
        const int c2 = tid;
        float m = -1e30f;
#pragma unroll
        for (int r = 0; r < VV; r++) m = fmaxf(m, sl[r * VV + c2]);
        float sum = 0.f;
#pragma unroll
        for (int r = 0; r < VV; r++) sum += expf(sl[r * VV + c2] - m);
        float inv = 1.f / sum;
        const float* af = g_Afull + s * VV * VV;
        float* a1o = g_A1 + (size_t)(s * NB + n) * VV * VV;
#pragma unroll
        for (int r = 0; r < VV; r++)
            a1o[r * VV + c2] = af[r * VV + c2] + expf(sl[r * VV + c2] - m) * inv;
    }
}

// ---------------------------------------------------------------------------
// K3 v6: double-buffered aggz.  Per subset: issue stage(s+1) -> compute(s)
//        -> ONE __syncthreads.  Barriers 6 -> 3; staging latency hidden under
//        compute; phase fences preserved (avoids R14 register explosion).
//        Arithmetic identical to v4/v5.
// grid: (30, N), block 256; smem 89896 B, 2 CTA/SM
// ---------------------------------------------------------------------------
#define TT2 10
__global__ __launch_bounds__(256, 2)
void k_aggz(const float* __restrict__ x,
            const float* __restrict__ Wd, const float* __restrict__ bd,
            const float* __restrict__ weights,
            const float* __restrict__ bng, const float* __restrict__ bnb,
            const float* __restrict__ bnm, const float* __restrict__ bnv,
            float* __restrict__ out) {
    extern __shared__ float sm[];
    float*   xs    = sm;                        // 17000
    __half2* sWdh  = (__half2*)(sm + 17000);    // 2 buffers x 2048 half2 (16 KB)
    float*   A1s   = sm + 17000 + 4096;         // 2 buffers x 625
    float*   ka    = A1s + 1250;                // 64
    float*   kb    = ka + 64;                   // 64

    const int n  = blockIdx.y;
    const int t0 = blockIdx.x * TT2;
    const int tid = threadIdx.x;
    const int nb = n * CCH * TV;

    // ---- initial stage: xs, ka/kb, and subset 0 into buffer 0 ----
    for (int idx = tid; idx < CCH * TT2 * VV; idx += 256) {
        int ci = idx / (TT2 * VV);
        int tv = idx - ci * (TT2 * VV);
        xs[tv * 68 + ci] = x[nb + ci * TV + t0 * VV + tv];
    }
    for (int idx = tid; idx < CCH * 32; idx += 256) {
        int ci = idx >> 5;
        int cp = idx & 31;
        float w0 = Wd[(2 * cp) * CCH + ci];
        float w1 = Wd[(2 * cp + 1) * CCH + ci];
        sWdh[idx] = __floats2half2_rn(w0, w1);
    }
    for (int idx = tid; idx < VV * VV; idx += 256)
        A1s[idx] = g_A1[(size_t)n * (VV * VV) + idx];
    if (tid < CCH) {
        int co = tid;
        float ws1 = weights[1], ws2 = weights[2], ws3 = weights[3], ws4 = weights[4];
        // slim splits for out_c=64: 38, 44, 51, 57
        float sc = (co < 38) ? 1.f : (co < 44) ? ws1 : (co < 51) ? ws2 : (co < 57) ? ws3 : ws4;
        float bdsum = bd[co] + bd[CCH + co] + bd[2 * CCH + co];
        float fa = bng[co] * rsqrtf(bnv[co] + 1e-5f);
        ka[co] = fa * sc;
        kb[co] = fa * sc * bdsum + bnb[co] - bnm[co] * fa;
    }
    __syncthreads();

    uint64_t zacc[32];
    const uint64_t z2 = pack2(0.f, 0.f);
#pragma unroll
    for (int i = 0; i < 32; i++) zacc[i] = z2;

    const int tv = tid;
    const bool act = tid < TT2 * VV;
    const int tloc = tv / 25;
    const int v2 = tv - tloc * 25;
    const half2 hz = __float2half2_rn(0.f);

    for (int s = 0; s < SS; s++) {
        const int buf = s & 1;
        // ---- issue stage of subset s+1 into the alternate buffer ----
        if (s + 1 < SS) {
            const int nxt = s + 1;
            const int ab = buf ^ 1;
            for (int idx = tid; idx < CCH * 32; idx += 256) {
                int ci = idx >> 5;
                int cp = idx & 31;
                float w0 = Wd[(nxt * CCH + 2 * cp) * CCH + ci];
                float w1 = Wd[(nxt * CCH + 2 * cp + 1) * CCH + ci];
                sWdh[ab * 2048 + idx] = __floats2half2_rn(w0, w1);
            }
            for (int idx = tid; idx < VV * VV; idx += 256)
                A1s[ab * 625 + idx] = g_A1[(size_t)(nxt * NB + n) * (VV * VV) + idx];
        }

        // ---- compute subset s from the current buffer ----
        if (act) {
            const float*   A1b = A1s + buf * 625;
            const __half2* Wb  = sWdh + buf * 2048;
#pragma unroll
            for (int cb = 0; cb < 64; cb += 16) {
                // agg phase (fp32)
                uint64_t ap[8];
#pragma unroll
                for (int i = 0; i < 8; i++) ap[i] = z2;
#pragma unroll
                for (int vv1 = 0; vv1 < VV; vv1++) {
                    float aw = A1b[vv1 * VV + v2];
                    uint64_t awp = pack2(aw, aw);
                    const ulonglong2* xp = (const ulonglong2*)(xs + (tloc * 25 + vv1) * 68 + cb);
#pragma unroll
                    for (int q = 0; q < 4; q++) {
                        ulonglong2 xv = xp[q];
                        fma2(ap[2*q],   xv.x, awp);
                        fma2(ap[2*q+1], xv.y, awp);
                    }
                }
                // fold phase (fp16 HFMA2) — two co-halves, zh[16] each
#pragma unroll
                for (int ch = 0; ch < 2; ch++) {
                    half2 zh[16];
#pragma unroll
                    for (int i = 0; i < 16; i++) zh[i] = hz;
#pragma unroll
                    for (int i = 0; i < 8; i++) {
                        float2 af = unpack2(ap[i]);
                        half2 a0 = __float2half2_rn(af.x);
                        half2 a1 = __float2half2_rn(af.y);
                        const uint4* w0 = (const uint4*)(Wb + (cb + 2 * i) * 32 + ch * 16);
                        const uint4* w1 = (const uint4*)(Wb + (cb + 2 * i + 1) * 32 + ch * 16);
#pragma unroll
                        for (int q = 0; q < 4; q++) {
                            half2 w4[4];
                            *(uint4*)w4 = w0[q];
                            zh[4*q+0] = __hfma2(w4[0], a0, zh[4*q+0]);
                            zh[4*q+1] = __hfma2(w4[1], a0, zh[4*q+1]);
                            zh[4*q+2] = __hfma2(w4[2], a0, zh[4*q+2]);
                            zh[4*q+3] = __hfma2(w4[3], a0, zh[4*q+3]);
                        }
#pragma unroll
                        for (int q = 0; q < 4; q++) {
                            half2 w4[4];
                            *(uint4*)w4 = w1[q];
                            zh[4*q+0] = __hfma2(w4[0], a1, zh[4*q+0]);
                            zh[4*q+1] = __hfma2(w4[1], a1, zh[4*q+1]);
                            zh[4*q+2] = __hfma2(w4[2], a1, zh[4*q+2]);
                            zh[4*q+3] = __hfma2(w4[3], a1, zh[4*q+3]);
                        }
                    }
#pragma unroll
                    for (int cp = 0; cp < 16; cp++) {
                        float2 f = __half22float2(zh[cp]);
                        add2(zacc[ch * 16 + cp], pack2(f.x, f.y));
                    }
                }
            }
        }
        __syncthreads();   // stage(s+1) complete + compute(s) done before buf reuse
    }

    if (act) {
        const float* xrow = xs + (tloc * 25 + v2) * 68;
        const int ob = nb + t0 * VV + tv;
#pragma unroll
        for (int cp = 0; cp < 32; cp++) {
            float2 zz = unpack2(zacc[cp]);
            int c0 = 2 * cp, c1 = 2 * cp + 1;
            float val0 = ka[c0] * zz.x + kb[c0] + xrow[c0];
            float val1 = ka[c1] * zz.y + kb[c1] + xrow[c1];
            out[ob + c0 * TV] = fmaxf(val0, 0.f);
            out[ob + c1 * TV] = fmaxf(val1, 0.f);
        }
    }
}

// ---------------------------------------------------------------------------
// launch
// ---------------------------------------------------------------------------
extern "C" void kernel_launch(void* const* d_in, const int* in_sizes, int n_in,
                              void* d_out, int out_size) {
    const float* x    = (const float*)d_in[0];
    const float* wts  = (const float*)d_in[1];
    const float* A    = (const float*)d_in[2];
    const float* PA   = (const float*)d_in[3];
    const float* Wd   = (const float*)d_in[4];
    const float* bd   = (const float*)d_in[5];
    const float* WT1  = (const float*)d_in[6];
    const float* bT1  = (const float*)d_in[7];
    const float* WT2  = (const float*)d_in[8];
    const float* bT2  = (const float*)d_in[9];
    const float* bng  = (const float*)d_in[10];
    const float* bnb  = (const float*)d_in[11];
    const float* bnm  = (const float*)d_in[12];
    const float* bnv  = (const float*)d_in[13];
    float* out = (float*)d_out;

    const int conv_smem = 576 * 32 * 4;                          // 73728
    const int aggz_smem = (17000 + 4096 + 1250 + 128) * 4;       // 89896
    cudaFuncSetAttribute(k_conv, cudaFuncAttributeMaxDynamicSharedMemorySize, conv_smem);
    cudaFuncSetAttribute(k_aggz, cudaFuncAttributeMaxDynamicSharedMemorySize, aggz_smem);

    k_afull<<<1, 640>>>(A, PA);
    k_wprep<<<54, 1024>>>(WT1, WT2);
    k_conv<<<dim3(6, NB, SS), 250, conv_smem>>>(x, bT1, bT2, wts);
    k_att2<<<dim3(NB, SS, KS), 640>>>();
    k_soft<<<dim3(NB, SS), 640>>>();
    k_aggz<<<dim3(TT / TT2, NB), 256, aggz_smem>>>(x, Wd, bd, wts, bng, bnb, bnm, bnv, out);
}

// round 16
// speedup vs baseline: 2.7893x; 2.7893x over previous
#include <cuda_runtime.h>
#include <cuda_fp16.h>
#include <math.h>
#include <stdint.h>

// ---------------------------------------------------------------------------
// Problem constants
// ---------------------------------------------------------------------------
#define NB   64
#define CCH  64
#define TT   300
#define VV   25
#define SS   3
#define IC   16
#define TV   (TT*VV)          // 7500
#define KROWS (IC*TT)         // 4800
#define KS   3
#define KPB  (KROWS/KS)       // 1600
#define ACH  320              // staged chunk (k-rows); 5 chunks per block
#define TSTR 326              // smem row stride in halfs (163 half2, odd -> conflict-free)

// Scratch (device globals — no allocation allowed)
__device__ __half  g_t1h[SS * NB * IC * TV];
__device__ __half  g_t2h[SS * NB * IC * TV];
__device__ float   g_A1[SS * NB * VV * VV];
__device__ float   g_Afull[SS * VV * VV];
__device__ __half2 g_Whd[SS * 576 * 32];
__device__ float   g_plog[SS * NB * KS * 640];

// ---------------------------------------------------------------------------
// Packed fp32x2 helpers
// ---------------------------------------------------------------------------
__device__ __forceinline__ void fma2(uint64_t& d, uint64_t a, uint64_t b) {
    asm("fma.rn.f32x2 %0, %1, %2, %0;" : "+l"(d) : "l"(a), "l"(b));
}
__device__ __forceinline__ void add2(uint64_t& d, uint64_t a) {
    asm("add.rn.f32x2 %0, %0, %1;" : "+l"(d) : "l"(a));
}
__device__ __forceinline__ uint64_t pack2(float lo, float hi) {
    uint64_t r;
    asm("mov.b64 %0, {%1, %2};" : "=l"(r) : "f"(lo), "f"(hi));
    return r;
}
__device__ __forceinline__ float2 unpack2(uint64_t v) {
    float2 r;
    asm("mov.b64 {%0, %1}, %2;" : "=f"(r.x), "=f"(r.y) : "l"(v));
    return r;
}

// ---------------------------------------------------------------------------
// K0: A_full = A + PA + (8A^4 - 4A^2 - 4A + I)
// ---------------------------------------------------------------------------
__global__ void k_afull(const float* __restrict__ A, const float* __restrict__ PA) {
    for (int idx = threadIdx.x; idx < SS * VV * VV; idx += blockDim.x) {
        int r = idx % (VV * VV);
        int v1 = r / VV, v2 = r % VV;
        float a = A[idx];
        float a2 = a * a;
        float ch = 8.f * a2 * a2 - 4.f * a2 - 4.f * a + (v1 == v2 ? 1.f : 0.f);
        g_Afull[idx] = a + PA[idx] + ch;
    }
}

// ---------------------------------------------------------------------------
// K0b: pre-duplicate conv weights to half2(w,w)
// ---------------------------------------------------------------------------
__global__ void k_wprep(const float* __restrict__ WT1, const float* __restrict__ WT2) {
    for (int idx = threadIdx.x + blockIdx.x * blockDim.x; idx < SS * 576 * 32;
         idx += blockDim.x * gridDim.x) {
        int slot = idx & 31;
        int kd   = (idx >> 5) % 576;
        int s    = idx / (576 * 32);
        int ci = kd / 9, dt = kd - 9 * (kd / 9);
        int cv = slot >> 4, co = slot & 15;
        float w = cv ? WT2[((s * IC + co) * CCH + ci) * 9 + dt]
                     : WT1[((s * IC + co) * CCH + ci) * 9 + dt];
        __half h = __float2half(w);
        g_Whd[idx] = __halves2half2(h, h);
    }
}

// ---------------------------------------------------------------------------
// K1 v7: slim_conv HFMA2. Thread = 16 co-slots x 10 t (one full conv).
// grid (6, N, S); block 250; smem 73728 B; 2 CTAs/SM.
// ---------------------------------------------------------------------------
__global__ __launch_bounds__(250, 2)
void k_conv(const float* __restrict__ x,
            const float* __restrict__ bT1, const float* __restrict__ bT2,
            const float* __restrict__ weights) {
    const int s = blockIdx.z;
    const int n = blockIdx.y;
    extern __shared__ __half2 sw[];   // 576*32 half2 = 73728 B

    {
        const uint4* src = (const uint4*)(g_Whd + s * 576 * 32);
        uint4* dst = (uint4*)sw;
        for (int i = threadIdx.x; i < 576 * 32 / 4; i += 250) dst[i] = src[i];
    }
    __syncthreads();

    const int tid = threadIdx.x;
    const int cog = tid / 125;           // 0..1  (= cv)
    const int r   = tid - cog * 125;
    const int tg  = r / 25;              // 0..4
    const int v   = r - tg * 25;
    const int t0  = blockIdx.x * 50 + tg * 10;
    const bool interior = (t0 >= 4) && (t0 + 13 < TT);

    half2 hacc[80];                      // [j 0..15][tp 0..4]
    const half2 hz = __float2half2_rn(0.f);
#pragma unroll
    for (int i = 0; i < 80; i++) hacc[i] = hz;

    const float* xb = x + n * CCH * TV + v;

    for (int ci = 0; ci < CCH; ci++) {
        const float* xp = xb + ci * TV + (t0 - 4) * VV;
        float xr[18];
        if (interior) {
#pragma unroll
            for (int k = 0; k < 18; k++) xr[k] = __ldg(xp + k * VV);
        } else {
#pragma unroll
            for (int k = 0; k < 18; k++) {
                int tt = t0 - 4 + k;
                xr[k] = (tt >= 0 && tt < TT) ? __ldg(xp + k * VV) : 0.f;
            }
        }
        half2 xe[9], xo[8];
#pragma unroll
        for (int j = 0; j < 9; j++) xe[j] = __floats2half2_rn(xr[2 * j], xr[2 * j + 1]);
#pragma unroll
        for (int j = 0; j < 8; j++) xo[j] = __floats2half2_rn(xr[2 * j + 1], xr[2 * j + 2]);

#pragma unroll
        for (int dt = 0; dt < 9; dt++) {
            const uint4* wp = (const uint4*)(sw + (ci * 9 + dt) * 32 + cog * 16);
            half2 w[16];
            *(uint4*)(w)      = wp[0];
            *(uint4*)(w + 4)  = wp[1];
            *(uint4*)(w + 8)  = wp[2];
            *(uint4*)(w + 12) = wp[3];
            const half2* xv = (dt & 1) ? (xo + (dt >> 1)) : (xe + (dt >> 1));
#pragma unroll
            for (int j = 0; j < 16; j++) {
#pragma unroll
                for (int tp = 0; tp < 5; tp++) {
                    hacc[j * 5 + tp] = __hfma2(w[j], xv[tp], hacc[j * 5 + tp]);
                }
            }
        }
    }

    const float ws1 = __ldg(weights + 1), ws2 = __ldg(weights + 2);
    const float ws3 = __ldg(weights + 3), ws4 = __ldg(weights + 4);
    const float* bsrc = cog ? bT2 : bT1;
    __half* gout = cog ? g_t2h : g_t1h;
    const size_t obase = (size_t)(s * NB + n) * IC * TV + v;
#pragma unroll
    for (int j = 0; j < 16; j++) {
        int co = j;
        // slim splits for out_c=16: 9, 11, 12, 14
        float sc = (co < 9) ? 1.f : (co < 11) ? ws1 : (co < 12) ? ws2 : (co < 14) ? ws3 : ws4;
        float b = __ldg(bsrc + s * IC + co);
        size_t oc = obase + (size_t)co * TV + (size_t)t0 * VV;
#pragma unroll
        for (int tp = 0; tp < 5; tp++) {
            float2 f = __half22float2(hacc[j * 5 + tp]);
            gout[oc + (2 * tp) * VV]     = __float2half(sc * (f.x + b));
            gout[oc + (2 * tp + 1) * VV] = __float2half(sc * (f.y + b));
        }
    }
}

// ---------------------------------------------------------------------------
// K2a: attention partial logits.  grid (N, S, KS), block 640.
//   ACH=320 chunks (5 per block): half the barriers of the ACH=160 version.
//   fp16 chunk-accumulator boundaries unchanged (every 16 half2) -> identical
//   arithmetic to R13.
// ---------------------------------------------------------------------------
__global__ __launch_bounds__(640, 2)
void k_att2() {
    const int n  = blockIdx.x;
    const int s  = blockIdx.y;
    const int kc = blockIdx.z;
    __shared__ __half s1t[25 * TSTR];
    __shared__ __half s2t[25 * TSTR];

    const __half* t1b = g_t1h + (size_t)(s * NB + n) * IC * TV;
    const __half* t2b = g_t2h + (size_t)(s * NB + n) * IC * TV;

    const int tid = threadIdx.x;
    const int v1 = tid / 25;
    const int v2 = tid - v1 * 25;
    const bool act = tid < VV * VV;
    float acc = 0.f;

    for (int ch = 0; ch < KPB / ACH; ch++) {
        const int kbase = kc * KPB + ch * ACH;
        for (int idx = tid; idx < ACH * VV; idx += 640) {
            int kk = idx / VV;
            int v  = idx - kk * VV;
            int k  = kbase + kk;
            int c  = k / TT;
            int t  = k - c * TT;
            int off = c * TV + t * VV + v;
            s1t[v * TSTR + kk] = t1b[off];
            s2t[v * TSTR + kk] = t2b[off];
        }
        __syncthreads();
        if (act) {
            const half2* p1 = (const half2*)s1t + v1 * (TSTR / 2);
            const half2* p2 = (const half2*)s2t + v2 * (TSTR / 2);
#pragma unroll
            for (int g = 0; g < 10; g++) {
                half2 ph = __float2half2_rn(0.f);
#pragma unroll
                for (int j = 0; j < 16; j++)
                    ph = __hfma2(p1[g * 16 + j], p2[g * 16 + j], ph);
                float2 f = __half22float2(ph);
                acc += f.x + f.y;
            }
        }
        __syncthreads();
    }

    g_plog[((size_t)(s * NB + n) * KS + kc) * 640 + tid] = acc;
}

// ---------------------------------------------------------------------------
// K2b: reduce partials + softmax(axis=-2 over v1) + A_full -> A1
// ---------------------------------------------------------------------------
__global__ __launch_bounds__(640, 2)
void k_soft() {
    const int n = blockIdx.x;
    const int s = blockIdx.y;
    __shared__ float sl[VV * VV];
    const int tid = threadIdx.x;

    if (tid < VV * VV) {
        const float* pb = g_plog + (size_t)(s * NB + n) * KS * 640 + tid;
        float a = pb[0] + pb[640] + pb[1280];
        sl[tid] = a * (1.0f / (float)KROWS);
    }
    __syncthreads();

    if (tid < VV) {
        const int c2 = tid;
        float m = -1e30f;
#pragma unroll
        for (int r = 0; r < VV; r++) m = fmaxf(m, sl[r * VV + c2]);
        float sum = 0.f;
#pragma unroll
        for (int r = 0; r < VV; r++) sum += expf(sl[r * VV + c2] - m);
        float inv = 1.f / sum;
        const float* af = g_Afull + s * VV * VV;
        float* a1o = g_A1 + (size_t)(s * NB + n) * VV * VV;
#pragma unroll
        for (int r = 0; r < VV; r++)
            a1o[r * VV + c2] = af[r * VV + c2] + expf(sl[r * VV + c2] - m) * inv;
    }
}

// ---------------------------------------------------------------------------
// K3 v4 (R13, best known): agg (fp32 FFMA2) + Wd fold (fp16 HFMA2, zh[16]
//        co-half split) + epilogue.  Per-subset barriers retained — they are
//        load-bearing register-pressure fences (R14/R15 post-mortems).
// grid: (30, N), block 256; smem ~79 KB, 2 CTA/SM
// ---------------------------------------------------------------------------
#define TT2 10
__global__ __launch_bounds__(256, 2)
void k_aggz(const float* __restrict__ x,
            const float* __restrict__ Wd, const float* __restrict__ bd,
            const float* __restrict__ weights,
            const float* __restrict__ bng, const float* __restrict__ bnb,
            const float* __restrict__ bnm, const float* __restrict__ bnv,
            float* __restrict__ out) {
    extern __shared__ float sm[];
    float*   xs   = sm;                        // 250*68 = 17000
    __half2* sWdh = (__half2*)(sm + 17000);    // 64 ci x 32 co-pairs (8 KB)
    float*   A1s  = sm + 17000 + 2048;         // 625
    float*   ka   = A1s + 625;                 // 64
    float*   kb   = ka + 64;                   // 64

    const int n  = blockIdx.y;
    const int t0 = blockIdx.x * TT2;
    const int tid = threadIdx.x;
    const int nb = n * CCH * TV;

    for (int idx = tid; idx < CCH * TT2 * VV; idx += 256) {
        int ci = idx / (TT2 * VV);
        int tv = idx - ci * (TT2 * VV);
        xs[tv * 68 + ci] = x[nb + ci * TV + t0 * VV + tv];
    }
    if (tid < CCH) {
        int co = tid;
        float ws1 = weights[1], ws2 = weights[2], ws3 = weights[3], ws4 = weights[4];
        // slim splits for out_c=64: 38, 44, 51, 57
        float sc = (co < 38) ? 1.f : (co < 44) ? ws1 : (co < 51) ? ws2 : (co < 57) ? ws3 : ws4;
        float bdsum = bd[co] + bd[CCH + co] + bd[2 * CCH + co];
        float fa = bng[co] * rsqrtf(bnv[co] + 1e-5f);
        ka[co] = fa * sc;
        kb[co] = fa * sc * bdsum + bnb[co] - bnm[co] * fa;
    }

    uint64_t zacc[32];
    const uint64_t z2 = pack2(0.f, 0.f);
#pragma unroll
    for (int i = 0; i < 32; i++) zacc[i] = z2;

    const int tv = tid;
    const bool act = tid < TT2 * VV;
    const int tloc = tv / 25;
    const int v2 = tv - tloc * 25;
    const half2 hz = __float2half2_rn(0.f);

    for (int s = 0; s < SS; s++) {
        __syncthreads();
        for (int idx = tid; idx < CCH * 32; idx += 256) {
            int ci = idx >> 5;
            int cp = idx & 31;
            float w0 = Wd[(s * CCH + 2 * cp) * CCH + ci];
            float w1 = Wd[(s * CCH + 2 * cp + 1) * CCH + ci];
            sWdh[ci * 32 + cp] = __floats2half2_rn(w0, w1);
        }
        for (int idx = tid; idx < VV * VV; idx += 256)
            A1s[idx] = g_A1[(size_t)(s * NB + n) * VV * VV + idx];
        __syncthreads();

        if (act) {
#pragma unroll
            for (int cb = 0; cb < 64; cb += 16) {
                // agg phase (fp32)
                uint64_t ap[8];
#pragma unroll
                for (int i = 0; i < 8; i++) ap[i] = z2;
#pragma unroll
                for (int vv1 = 0; vv1 < VV; vv1++) {
                    float aw = A1s[vv1 * VV + v2];
                    uint64_t awp = pack2(aw, aw);
                    const ulonglong2* xp = (const ulonglong2*)(xs + (tloc * 25 + vv1) * 68 + cb);
#pragma unroll
                    for (int q = 0; q < 4; q++) {
                        ulonglong2 xv = xp[q];
                        fma2(ap[2*q],   xv.x, awp);
                        fma2(ap[2*q+1], xv.y, awp);
                    }
                }
                // fold phase (fp16 HFMA2) — two co-halves, zh[16] each
#pragma unroll
                for (int ch = 0; ch < 2; ch++) {
                    half2 zh[16];
#pragma unroll
                    for (int i = 0; i < 16; i++) zh[i] = hz;
#pragma unroll
                    for (int i = 0; i < 8; i++) {
                        float2 af = unpack2(ap[i]);
                        half2 a0 = __float2half2_rn(af.x);
                        half2 a1 = __float2half2_rn(af.y);
                        const uint4* w0 = (const uint4*)(sWdh + (cb + 2 * i) * 32 + ch * 16);
                        const uint4* w1 = (const uint4*)(sWdh + (cb + 2 * i + 1) * 32 + ch * 16);
#pragma unroll
                        for (int q = 0; q < 4; q++) {
                            half2 w4[4];
                            *(uint4*)w4 = w0[q];
                            zh[4*q+0] = __hfma2(w4[0], a0, zh[4*q+0]);
                            zh[4*q+1] = __hfma2(w4[1], a0, zh[4*q+1]);
                            zh[4*q+2] = __hfma2(w4[2], a0, zh[4*q+2]);
                            zh[4*q+3] = __hfma2(w4[3], a0, zh[4*q+3]);
                        }
#pragma unroll
                        for (int q = 0; q < 4; q++) {
                            half2 w4[4];
                            *(uint4*)w4 = w1[q];
                            zh[4*q+0] = __hfma2(w4[0], a1, zh[4*q+0]);
                            zh[4*q+1] = __hfma2(w4[1], a1, zh[4*q+1]);
                            zh[4*q+2] = __hfma2(w4[2], a1, zh[4*q+2]);
                            zh[4*q+3] = __hfma2(w4[3], a1, zh[4*q+3]);
                        }
                    }
#pragma unroll
                    for (int cp = 0; cp < 16; cp++) {
                        float2 f = __half22float2(zh[cp]);
                        add2(zacc[ch * 16 + cp], pack2(f.x, f.y));
                    }
                }
            }
        }
    }

    if (act) {
        const float* xrow = xs + (tloc * 25 + v2) * 68;
        const int ob = nb + t0 * VV + tv;
#pragma unroll
        for (int cp = 0; cp < 32; cp++) {
            float2 zz = unpack2(zacc[cp]);
            int c0 = 2 * cp, c1 = 2 * cp + 1;
            float val0 = ka[c0] * zz.x + kb[c0] + xrow[c0];
            float val1 = ka[c1] * zz.y + kb[c1] + xrow[c1];
            out[ob + c0 * TV] = fmaxf(val0, 0.f);
            out[ob + c1 * TV] = fmaxf(val1, 0.f);
        }
    }
}

// ---------------------------------------------------------------------------
// launch
// ---------------------------------------------------------------------------
extern "C" void kernel_launch(void* const* d_in, const int* in_sizes, int n_in,
                              void* d_out, int out_size) {
    const float* x    = (const float*)d_in[0];
    const float* wts  = (const float*)d_in[1];
    const float* A    = (const float*)d_in[2];
    const float* PA   = (const float*)d_in[3];
    const float* Wd   = (const float*)d_in[4];
    const float* bd   = (const float*)d_in[5];
    const float* WT1  = (const float*)d_in[6];
    const float* bT1  = (const float*)d_in[7];
    const float* WT2  = (const float*)d_in[8];
    const float* bT2  = (const float*)d_in[9];
    const float* bng  = (const float*)d_in[10];
    const float* bnb  = (const float*)d_in[11];
    const float* bnm  = (const float*)d_in[12];
    const float* bnv  = (const float*)d_in[13];
    float* out = (float*)d_out;

    const int conv_smem = 576 * 32 * 4;                          // 73728
    const int aggz_smem = (17000 + 2048 + 625 + 128) * 4;        // 79204
    cudaFuncSetAttribute(k_conv, cudaFuncAttributeMaxDynamicSharedMemorySize, conv_smem);
    cudaFuncSetAttribute(k_aggz, cudaFuncAttributeMaxDynamicSharedMemorySize, aggz_smem);

    k_afull<<<1, 640>>>(A, PA);
    k_wprep<<<54, 1024>>>(WT1, WT2);
    k_conv<<<dim3(6, NB, SS), 250, conv_smem>>>(x, bT1, bT2, wts);
    k_att2<<<dim3(NB, SS, KS), 640>>>();
    k_soft<<<dim3(NB, SS), 640>>>();
    k_aggz<<<dim3(TT / TT2, NB), 256, aggz_smem>>>(x, Wd, bd, wts, bng, bnb, bnm, bnv, out);
}